// round 10
// baseline (speedup 1.0000x reference)
#include <cuda_runtime.h>
#include <cuda_fp16.h>
#include <cstdint>
#include <math.h>

#define BATCH  4
#define SEQ    2048
#define DMODEL 1024
#define NHEADS 16
#define HDIM   64
#define MROWS  (BATCH * SEQ)

// Scratch (allocation-free)
__device__ __half g_xh[MROWS * DMODEL];
__device__ __half g_qh[MROWS * DMODEL];
__device__ __half g_kh[MROWS * DMODEL];
__device__ __half g_vh[MROWS * DMODEL];
__device__ __half g_oh[MROWS * DMODEL];
__device__ __half g_wh[4][DMODEL * DMODEL];   // wq, wk, wv, wo as fp16

// ---------------------------------------------------------------------------
// Helpers
// ---------------------------------------------------------------------------
__device__ __forceinline__ uint32_t smem_u32(const void* p) {
    uint32_t a;
    asm("{ .reg .u64 t; cvta.to.shared.u64 t, %1; cvt.u32.u64 %0, t; }"
        : "=r"(a) : "l"(p));
    return a;
}

__device__ __forceinline__ void cp_async16(uint32_t dst, const void* src) {
    asm volatile("cp.async.cg.shared.global [%0], [%1], 16;"
                 :: "r"(dst), "l"(src));
}
#define CP_COMMIT() asm volatile("cp.async.commit_group;" ::: "memory")
#define CP_WAIT1()  asm volatile("cp.async.wait_group 1;" ::: "memory")
#define CP_WAIT0()  asm volatile("cp.async.wait_group 0;" ::: "memory")

__device__ __forceinline__ void mma_f16_16n8k16(float* c, const uint32_t* a,
                                                const uint32_t* b) {
    asm volatile(
        "mma.sync.aligned.m16n8k16.row.col.f32.f16.f16.f32 "
        "{%0,%1,%2,%3}, {%4,%5,%6,%7}, {%8,%9}, {%0,%1,%2,%3};"
        : "+f"(c[0]), "+f"(c[1]), "+f"(c[2]), "+f"(c[3])
        : "r"(a[0]), "r"(a[1]), "r"(a[2]), "r"(a[3]), "r"(b[0]), "r"(b[1]));
}

__device__ __forceinline__ void ldsm_x4(uint32_t& r0, uint32_t& r1,
                                        uint32_t& r2, uint32_t& r3,
                                        uint32_t addr) {
    asm volatile("ldmatrix.sync.aligned.m8n8.x4.shared.b16 {%0,%1,%2,%3}, [%4];"
                 : "=r"(r0), "=r"(r1), "=r"(r2), "=r"(r3) : "r"(addr));
}

__device__ __forceinline__ void ldsm_x4_t(uint32_t& r0, uint32_t& r1,
                                          uint32_t& r2, uint32_t& r3,
                                          uint32_t addr) {
    asm volatile("ldmatrix.sync.aligned.m8n8.x4.trans.shared.b16 {%0,%1,%2,%3}, [%4];"
                 : "=r"(r0), "=r"(r1), "=r"(r2), "=r"(r3) : "r"(addr));
}

__device__ __forceinline__ uint32_t h2u(float a, float b) {
    __half2 h = __floats2half2_rn(a, b);
    return *(uint32_t*)&h;
}

// ---------------------------------------------------------------------------
// Fused fp32 -> fp16 conversion: slice 0 = x (8M elems), 1..4 = weights (1M).
// ---------------------------------------------------------------------------
__global__ void f2h_all_kernel(const float* __restrict__ x,
                               const float* __restrict__ w0,
                               const float* __restrict__ w1,
                               const float* __restrict__ w2,
                               const float* __restrict__ w3,
                               __half* __restrict__ xh,
                               __half* __restrict__ wh) {
    const int j = blockIdx.y;
    const float* s;
    __half* d;
    int n4;
    if (j == 0) { s = x; d = xh; n4 = MROWS * DMODEL / 4; }
    else {
        s = (j == 1) ? w0 : (j == 2) ? w1 : (j == 3) ? w2 : w3;
        d = wh + (size_t)(j - 1) * DMODEL * DMODEL;
        n4 = DMODEL * DMODEL / 4;
    }
    int i = blockIdx.x * blockDim.x + threadIdx.x;
    if (i < n4) {
        float4 v = ((const float4*)s)[i];
        ((__half2*)d)[2 * i]     = __floats2half2_rn(v.x, v.y);
        ((__half2*)d)[2 * i + 1] = __floats2half2_rn(v.z, v.w);
    }
}

// ===========================================================================
// fp16 tensor-core GEMM:  C[M,1024] = scale * (A(f16) @ B(f16)^T)
// CTA 128x128, BK=64, 8 warps, warp 64x32, 3-stage cp.async, ldmatrix loads.
// ===========================================================================
#define GBM 128
#define GBN 128
#define BKH 64
#define SSTRH 72
#define STAGE_BYTES (2 * 128 * SSTRH * 2)        // 36864
#define SMEM_GEMM   (3 * STAGE_BYTES)            // 110592

template <typename OutT>
__device__ __forceinline__ void gemm_body(const __half* __restrict__ A,
                                          const __half* __restrict__ Bw,
                                          OutT* __restrict__ C, float scale,
                                          char* smemc) {
    const uint32_t sb = smem_u32(smemc);
    const int K = DMODEL, N = DMODEL;
    const int tid = threadIdx.x;
    const int wid = tid >> 5;
    const int lid = tid & 31;
    const int gid = lid >> 2;
    const int tig = lid & 3;
    const int wm  = wid >> 2;
    const int wn  = wid & 3;
    const int m0  = blockIdx.y * GBM;
    const int n0  = blockIdx.x * GBN;

    float acc[4][4][4];
#pragma unroll
    for (int i = 0; i < 4; i++)
#pragma unroll
        for (int j = 0; j < 4; j++)
#pragma unroll
            for (int r = 0; r < 4; r++) acc[i][j][r] = 0.0f;

    auto issue = [&](int stage, int ck) {
        const __half* Ag = A  + (size_t)m0 * K + ck * BKH;
        const __half* Bg = Bw + (size_t)n0 * K + ck * BKH;
        const uint32_t da = sb + stage * STAGE_BYTES;
        const uint32_t db = da + 128 * SSTRH * 2;
#pragma unroll
        for (int i = 0; i < 4; i++) {
            int idx = tid + i * 256;
            int row = idx >> 3;
            int c   = idx & 7;
            uint32_t so = (uint32_t)(row * SSTRH + c * 8) * 2;
            cp_async16(da + so, Ag + (size_t)row * K + c * 8);
            cp_async16(db + so, Bg + (size_t)row * K + c * 8);
        }
        CP_COMMIT();
    };

    const int NCH = K / BKH;                     // 16
    issue(0, 0);
    issue(1, 1);

    const int a_row = lid & 15;
    const int a_col = (lid >> 4) * 8;
    const int b_row = (lid & 7) + ((lid >> 4) & 1) * 8;
    const int b_col = ((lid >> 3) & 1) * 8;

    for (int ck = 0; ck < NCH; ck++) {
        if (ck + 1 < NCH) { CP_WAIT1(); } else { CP_WAIT0(); }
        __syncthreads();
        if (ck + 2 < NCH) issue((ck + 2) % 3, ck + 2);

        const uint32_t bufA = sb + (ck % 3) * STAGE_BYTES;
        const uint32_t bufB = bufA + 128 * SSTRH * 2;

#pragma unroll
        for (int kk = 0; kk < 4; kk++) {
            const int koff = kk * 16;
            uint32_t af[4][4], bf[4][2];
#pragma unroll
            for (int mt = 0; mt < 4; mt++) {
                uint32_t ad = bufA + 2 * (uint32_t)((wm * 64 + mt * 16 + a_row) * SSTRH
                                                    + koff + a_col);
                ldsm_x4(af[mt][0], af[mt][1], af[mt][2], af[mt][3], ad);
            }
#pragma unroll
            for (int p = 0; p < 2; p++) {
                uint32_t bd = bufB + 2 * (uint32_t)((wn * 32 + p * 16 + b_row) * SSTRH
                                                    + koff + b_col);
                ldsm_x4(bf[2 * p][0], bf[2 * p][1], bf[2 * p + 1][0],
                        bf[2 * p + 1][1], bd);
            }
#pragma unroll
            for (int mt = 0; mt < 4; mt++)
#pragma unroll
                for (int nt = 0; nt < 4; nt++)
                    mma_f16_16n8k16(acc[mt][nt], af[mt], bf[nt]);
        }
    }

#pragma unroll
    for (int mt = 0; mt < 4; mt++) {
#pragma unroll
        for (int nt = 0; nt < 4; nt++) {
            int row = m0 + wm * 64 + mt * 16 + gid;
            int col = n0 + wn * 32 + nt * 8 + 2 * tig;
            if (sizeof(OutT) == 4) {
                float* Cf = (float*)C;
                *(float2*)&Cf[(size_t)row * N + col] =
                    make_float2(acc[mt][nt][0] * scale, acc[mt][nt][1] * scale);
                *(float2*)&Cf[(size_t)(row + 8) * N + col] =
                    make_float2(acc[mt][nt][2] * scale, acc[mt][nt][3] * scale);
            } else {
                __half* Ch = (__half*)C;
                *(__half2*)&Ch[(size_t)row * N + col] =
                    __floats2half2_rn(acc[mt][nt][0] * scale, acc[mt][nt][1] * scale);
                *(__half2*)&Ch[(size_t)(row + 8) * N + col] =
                    __floats2half2_rn(acc[mt][nt][2] * scale, acc[mt][nt][3] * scale);
            }
        }
    }
}

// Fused QKV: grid (8, 64, 3)
__global__ __launch_bounds__(256)
void gemm_qkv_kernel(const __half* __restrict__ xh,
                     const __half* __restrict__ whBase,
                     __half* __restrict__ qh, __half* __restrict__ kh,
                     __half* __restrict__ vh) {
    extern __shared__ char smemc[];
    const int slot = blockIdx.z;
    const __half* Bw = whBase + (size_t)slot * DMODEL * DMODEL;
    __half* C = (slot == 0) ? qh : (slot == 1) ? kh : vh;
    const float scale = (slot == 0) ? 0.125f : 1.0f;
    gemm_body<__half>(xh, Bw, C, scale, smemc);
}

__global__ __launch_bounds__(256)
void gemm_out_kernel(const __half* __restrict__ A,
                     const __half* __restrict__ Bw,
                     float* __restrict__ C) {
    extern __shared__ char smemc[];
    gemm_body<float>(A, Bw, C, 1.0f, smemc);
}

// ===========================================================================
// Tensor-core flash attention. V loaded in native [s][d] layout; P·V B
// fragments built with ldmatrix.x4.trans (no V transpose kernel needed).
// grid (SEQ/128, NHEADS, BATCH), 128 threads = 4 warps; warp: 32 q-rows.
// ===========================================================================
#define FBKV 64
#define FSTR 72

__global__ __launch_bounds__(128)
void flash_tc_kernel(const __half* __restrict__ Qh,
                     const __half* __restrict__ Kh,
                     const __half* __restrict__ Vh,
                     const int*   __restrict__ am,
                     __half* __restrict__ O) {
    __shared__ __half Ks[2][FBKV * FSTR];
    __shared__ __half Vs[2][FBKV * FSTR];
    __shared__ float  Ms[2][FBKV];

    const int tid = threadIdx.x;
    const int wid = tid >> 5;
    const int lid = tid & 31;
    const int gid = lid >> 2;
    const int tig = lid & 3;
    const int q0  = blockIdx.x * 128;
    const int h   = blockIdx.y;
    const int b   = blockIdx.z;
    const int qw0 = q0 + wid * 32;

    const uint32_t ksa = smem_u32(Ks);
    const uint32_t vsa = smem_u32(Vs);
    // non-trans (K) lane addressing
    const int b_row = (lid & 7) + ((lid >> 4) & 1) * 8;
    const int b_col = ((lid >> 3) & 1) * 8;
    // trans (V) lane addressing: row = k within 16, col = n-pair select
    const int t_row = (lid & 7) + ((lid >> 3) & 1) * 8;
    const int t_col = (lid >> 4) * 8;

    // Q fragments: 2 m-tiles x 4 k-tiles.
    uint32_t qf[2][4][4];
#pragma unroll
    for (int mt = 0; mt < 2; mt++)
#pragma unroll
        for (int kt = 0; kt < 4; kt++) {
            const __half* base = Qh + ((size_t)(b * SEQ) + qw0 + mt * 16 + gid) * DMODEL
                                    + h * 64 + kt * 16 + 2 * tig;
            qf[mt][kt][0] = *(const uint32_t*)base;
            qf[mt][kt][1] = *(const uint32_t*)(base + 8 * DMODEL);
            qf[mt][kt][2] = *(const uint32_t*)(base + 8);
            qf[mt][kt][3] = *(const uint32_t*)(base + 8 * DMODEL + 8);
        }

    float o[2][8][4];
#pragma unroll
    for (int mt = 0; mt < 2; mt++)
#pragma unroll
        for (int nt = 0; nt < 8; nt++)
#pragma unroll
            for (int r = 0; r < 4; r++) o[mt][nt][r] = 0.0f;
    float m_run[2][2] = { { -1e30f, -1e30f }, { -1e30f, -1e30f } };
    float lp[2][2]    = { { 0.0f, 0.0f }, { 0.0f, 0.0f } };

    const int nkb = (q0 + 128) / FBKV;

    auto issue = [&](int buf, int kb) {
        const int kv0 = kb * FBKV;
#pragma unroll
        for (int i = 0; i < 4; i++) {
            int idx = tid + i * 128;
            int row = idx >> 3;
            int c   = idx & 7;
            uint32_t so = (uint32_t)(buf * FBKV * FSTR + row * FSTR + c * 8) * 2;
            const size_t gb = ((size_t)(b * SEQ) + kv0 + row) * DMODEL + h * 64 + c * 8;
            cp_async16(ksa + so, Kh + gb);
            cp_async16(vsa + so, Vh + gb);
        }
        CP_COMMIT();
        if (tid < FBKV)
            Ms[buf][tid] = am[b * SEQ + kv0 + tid] ? 0.0f : -1e30f;
    };

    issue(0, 0);

    for (int kb = 0; kb < nkb; kb++) {
        if (kb + 1 < nkb) { issue((kb + 1) & 1, kb + 1); CP_WAIT1(); }
        else              { CP_WAIT0(); }
        __syncthreads();

        const int buf = kb & 1;
        const int kv0 = kb * FBKV;
        const uint32_t kbase = ksa + (uint32_t)(buf * FBKV * FSTR) * 2;
        const uint32_t vbase = vsa + (uint32_t)(buf * FBKV * FSTR) * 2;

        if (kv0 <= qw0 + 31) {                    // warp has unmasked work
            // ---- S = Q K^T ----
            float s[2][8][4];
#pragma unroll
            for (int mt = 0; mt < 2; mt++)
#pragma unroll
                for (int nt = 0; nt < 8; nt++)
#pragma unroll
                    for (int r = 0; r < 4; r++) s[mt][nt][r] = 0.0f;

#pragma unroll
            for (int kt = 0; kt < 4; kt++) {
                uint32_t bf[8][2];
#pragma unroll
                for (int p = 0; p < 4; p++) {
                    uint32_t ad = kbase + 2 * (uint32_t)((p * 16 + b_row) * FSTR
                                                         + kt * 16 + b_col);
                    ldsm_x4(bf[2 * p][0], bf[2 * p][1], bf[2 * p + 1][0],
                            bf[2 * p + 1][1], ad);
                }
#pragma unroll
                for (int mt = 0; mt < 2; mt++)
#pragma unroll
                    for (int nt = 0; nt < 8; nt++)
                        mma_f16_16n8k16(s[mt][nt], qf[mt][kt], bf[nt]);
            }

            // ---- mask + online softmax ----
#pragma unroll
            for (int mt = 0; mt < 2; mt++)
#pragma unroll
                for (int r = 0; r < 2; r++) {
                    const int row = qw0 + mt * 16 + gid + r * 8;
                    float mx = -1e30f;
#pragma unroll
                    for (int nt = 0; nt < 8; nt++)
#pragma unroll
                        for (int c = 0; c < 2; c++) {
                            const int jl = nt * 8 + 2 * tig + c;
                            float v = s[mt][nt][r * 2 + c] + Ms[buf][jl];
                            if (kv0 + jl > row) v = -1e30f;
                            s[mt][nt][r * 2 + c] = v;
                            mx = fmaxf(mx, v);
                        }
                    mx = fmaxf(mx, __shfl_xor_sync(0xffffffff, mx, 1));
                    mx = fmaxf(mx, __shfl_xor_sync(0xffffffff, mx, 2));
                    const float mnew = fmaxf(m_run[mt][r], mx);
                    const float corr = __expf(m_run[mt][r] - mnew);
                    m_run[mt][r] = mnew;
                    lp[mt][r] *= corr;
                    float ls = 0.0f;
#pragma unroll
                    for (int nt = 0; nt < 8; nt++) {
                        o[mt][nt][r * 2]     *= corr;
                        o[mt][nt][r * 2 + 1] *= corr;
                        float p0 = __expf(s[mt][nt][r * 2]     - mnew);
                        float p1 = __expf(s[mt][nt][r * 2 + 1] - mnew);
                        s[mt][nt][r * 2]     = p0;
                        s[mt][nt][r * 2 + 1] = p1;
                        ls += p0 + p1;
                    }
                    lp[mt][r] += ls;
                }

            // ---- O += P V  (V via trans ldmatrix from [s][d] tile) ----
#pragma unroll
            for (int kt = 0; kt < 4; kt++) {
                uint32_t bfv[8][2];
#pragma unroll
                for (int p = 0; p < 4; p++) {
                    uint32_t ad = vbase + 2 * (uint32_t)((kt * 16 + t_row) * FSTR
                                                         + p * 16 + t_col);
                    ldsm_x4_t(bfv[2 * p][0], bfv[2 * p][1], bfv[2 * p + 1][0],
                              bfv[2 * p + 1][1], ad);
                }
#pragma unroll
                for (int mt = 0; mt < 2; mt++) {
                    uint32_t pa[4];
                    pa[0] = h2u(s[mt][2 * kt][0],     s[mt][2 * kt][1]);
                    pa[1] = h2u(s[mt][2 * kt][2],     s[mt][2 * kt][3]);
                    pa[2] = h2u(s[mt][2 * kt + 1][0], s[mt][2 * kt + 1][1]);
                    pa[3] = h2u(s[mt][2 * kt + 1][2], s[mt][2 * kt + 1][3]);
#pragma unroll
                    for (int nt = 0; nt < 8; nt++)
                        mma_f16_16n8k16(o[mt][nt], pa, bfv[nt]);
                }
            }
        }
        __syncthreads();   // all warps done with buf before next issue overwrites it
    }

    // ---- epilogue ----
#pragma unroll
    for (int mt = 0; mt < 2; mt++)
#pragma unroll
        for (int r = 0; r < 2; r++) {
            float l = lp[mt][r];
            l += __shfl_xor_sync(0xffffffff, l, 1);
            l += __shfl_xor_sync(0xffffffff, l, 2);
            const float inv = 1.0f / l;
            const int row = qw0 + mt * 16 + gid + r * 8;
            __half* orow = O + ((size_t)(b * SEQ) + row) * DMODEL + h * 64;
#pragma unroll
            for (int nt = 0; nt < 8; nt++)
                *(__half2*)&orow[nt * 8 + 2 * tig] =
                    __floats2half2_rn(o[mt][nt][r * 2] * inv,
                                      o[mt][nt][r * 2 + 1] * inv);
        }
}

// ---------------------------------------------------------------------------
extern "C" void kernel_launch(void* const* d_in, const int* in_sizes, int n_in,
                              void* d_out, int out_size) {
    const float* x  = (const float*)d_in[0];
    const int*   am = (const int*)  d_in[1];
    float* out = (float*)d_out;

    __half *xh, *qh, *kh, *vh, *oh, *wh;
    cudaGetSymbolAddress((void**)&xh, g_xh);
    cudaGetSymbolAddress((void**)&qh, g_qh);
    cudaGetSymbolAddress((void**)&kh, g_kh);
    cudaGetSymbolAddress((void**)&vh, g_vh);
    cudaGetSymbolAddress((void**)&oh, g_oh);
    cudaGetSymbolAddress((void**)&wh, g_wh);

    cudaFuncSetAttribute(gemm_qkv_kernel,
                         cudaFuncAttributeMaxDynamicSharedMemorySize, SMEM_GEMM);
    cudaFuncSetAttribute(gemm_out_kernel,
                         cudaFuncAttributeMaxDynamicSharedMemorySize, SMEM_GEMM);

    {
        int nx4 = MROWS * DMODEL / 4;            // largest slice
        dim3 cg((nx4 + 255) / 256, 5);
        f2h_all_kernel<<<cg, 256>>>(x, (const float*)d_in[2], (const float*)d_in[3],
                                    (const float*)d_in[4], (const float*)d_in[5],
                                    xh, wh);
    }

    dim3 gq(DMODEL / GBN, MROWS / GBM, 3);    // (8, 64, 3)
    gemm_qkv_kernel<<<gq, 256, SMEM_GEMM>>>(xh, wh, qh, kh, vh);

    dim3 fg(SEQ / 128, NHEADS, BATCH);        // (16, 16, 4)
    flash_tc_kernel<<<fg, 128>>>(qh, kh, vh, am, oh);

    dim3 gg(DMODEL / GBN, MROWS / GBM);       // (8, 64)
    gemm_out_kernel<<<gg, 256, SMEM_GEMM>>>(
        oh, wh + 3 * (size_t)DMODEL * DMODEL, out);
}

// round 12
// speedup vs baseline: 1.4224x; 1.4224x over previous
#include <cuda_runtime.h>
#include <cuda_fp16.h>
#include <cstdint>
#include <math.h>

#define BATCH  4
#define SEQ    2048
#define DMODEL 1024
#define NHEADS 16
#define HDIM   64
#define MROWS  (BATCH * SEQ)

// Scratch (allocation-free)
__device__ __half g_xh[MROWS * DMODEL];
__device__ __half g_qh[MROWS * DMODEL];
__device__ __half g_kh[MROWS * DMODEL];
__device__ __half g_vh[MROWS * DMODEL];
__device__ __half g_vt[MROWS * DMODEL];       // V^T per (b,h)
__device__ __half g_oh[MROWS * DMODEL];
__device__ __half g_wh[4][DMODEL * DMODEL];   // wq, wk, wv, wo as fp16

// ---------------------------------------------------------------------------
// Helpers
// ---------------------------------------------------------------------------
__device__ __forceinline__ uint32_t smem_u32(const void* p) {
    uint32_t a;
    asm("{ .reg .u64 t; cvta.to.shared.u64 t, %1; cvt.u32.u64 %0, t; }"
        : "=r"(a) : "l"(p));
    return a;
}

__device__ __forceinline__ void cp_async16(uint32_t dst, const void* src) {
    asm volatile("cp.async.cg.shared.global [%0], [%1], 16;"
                 :: "r"(dst), "l"(src));
}
#define CP_COMMIT() asm volatile("cp.async.commit_group;" ::: "memory")
#define CP_WAIT1()  asm volatile("cp.async.wait_group 1;" ::: "memory")
#define CP_WAIT0()  asm volatile("cp.async.wait_group 0;" ::: "memory")

__device__ __forceinline__ void mma_f16_16n8k16(float* c, const uint32_t* a,
                                                const uint32_t* b) {
    asm volatile(
        "mma.sync.aligned.m16n8k16.row.col.f32.f16.f16.f32 "
        "{%0,%1,%2,%3}, {%4,%5,%6,%7}, {%8,%9}, {%0,%1,%2,%3};"
        : "+f"(c[0]), "+f"(c[1]), "+f"(c[2]), "+f"(c[3])
        : "r"(a[0]), "r"(a[1]), "r"(a[2]), "r"(a[3]), "r"(b[0]), "r"(b[1]));
}

__device__ __forceinline__ void ldsm_x4(uint32_t& r0, uint32_t& r1,
                                        uint32_t& r2, uint32_t& r3,
                                        uint32_t addr) {
    asm volatile("ldmatrix.sync.aligned.m8n8.x4.shared.b16 {%0,%1,%2,%3}, [%4];"
                 : "=r"(r0), "=r"(r1), "=r"(r2), "=r"(r3) : "r"(addr));
}

__device__ __forceinline__ uint32_t h2u(float a, float b) {
    __half2 h = __floats2half2_rn(a, b);
    return *(uint32_t*)&h;
}

// ---------------------------------------------------------------------------
// fp32 -> fp16 converters
// ---------------------------------------------------------------------------
__global__ void f2h_kernel(const float* __restrict__ s, __half* __restrict__ d,
                           int n4) {
    int i = blockIdx.x * blockDim.x + threadIdx.x;
    if (i < n4) {
        float4 v = ((const float4*)s)[i];
        ((__half2*)d)[2 * i]     = __floats2half2_rn(v.x, v.y);
        ((__half2*)d)[2 * i + 1] = __floats2half2_rn(v.z, v.w);
    }
}

__global__ void f2h4_kernel(const float* __restrict__ w0,
                            const float* __restrict__ w1,
                            const float* __restrict__ w2,
                            const float* __restrict__ w3,
                            __half* __restrict__ d, int n4) {
    const int j = blockIdx.y;
    const float* s = (j == 0) ? w0 : (j == 1) ? w1 : (j == 2) ? w2 : w3;
    __half* dd = d + (size_t)j * DMODEL * DMODEL;
    int i = blockIdx.x * blockDim.x + threadIdx.x;
    if (i < n4) {
        float4 v = ((const float4*)s)[i];
        ((__half2*)dd)[2 * i]     = __floats2half2_rn(v.x, v.y);
        ((__half2*)dd)[2 * i + 1] = __floats2half2_rn(v.z, v.w);
    }
}

// ---------------------------------------------------------------------------
// V transpose: v[b*SEQ+s][h*64+d] -> vt[(b*16+h)*64+d][s]
// ---------------------------------------------------------------------------
__global__ __launch_bounds__(256)
void vtrans_kernel(const __half* __restrict__ v, __half* __restrict__ vt) {
    __shared__ __half t[64][72];
    const int tid = threadIdx.x;
    const int s0 = blockIdx.x * 64;
    const int h  = blockIdx.y;
    const int b  = blockIdx.z;
#pragma unroll
    for (int i = 0; i < 2; i++) {
        int idx = tid + i * 256, row = idx >> 3, c = idx & 7;
        *(int4*)&t[row][c * 8] =
            *(const int4*)&v[((size_t)(b * SEQ) + s0 + row) * DMODEL + h * 64 + c * 8];
    }
    __syncthreads();
#pragma unroll
    for (int i = 0; i < 2; i++) {
        int idx = tid + i * 256, d = idx >> 3, c = idx & 7;
        __half tmp[8];
#pragma unroll
        for (int k = 0; k < 8; k++) tmp[k] = t[c * 8 + k][d];
        *(int4*)&vt[((size_t)((b * 16 + h) * 64) + d) * SEQ + s0 + c * 8] =
            *(int4*)tmp;
    }
}

// ===========================================================================
// fp16 tensor-core GEMM:  C[M,1024] = scale * (A(f16) @ B(f16)^T)
// CTA tile 256x128, BK=64, 512 threads (16 warps, 4x4), warp tile 64x32.
// 2-stage cp.async (double-sync ordering), ldmatrix fragment loads.
// Raises arithmetic intensity: 48 B L2 traffic per HMMA vs 64 at 128x128.
// ===========================================================================
#define GBM 256
#define GBN 128
#define BKH 64
#define SSTRH 72
#define SROWS (GBM + GBN)                        // 384 smem rows per stage
#define STAGE_BYTES (SROWS * SSTRH * 2)          // 55296
#define SMEM_GEMM   (2 * STAGE_BYTES)            // 110592

template <typename OutT>
__device__ __forceinline__ void gemm_body(const __half* __restrict__ A,
                                          const __half* __restrict__ Bw,
                                          OutT* __restrict__ C, float scale,
                                          char* smemc) {
    const uint32_t sb = smem_u32(smemc);
    const int K = DMODEL, N = DMODEL;
    const int tid = threadIdx.x;
    const int wid = tid >> 5;
    const int lid = tid & 31;
    const int gid = lid >> 2;
    const int tig = lid & 3;
    const int wm  = wid >> 2;                    // 0..3 : 64-row slab
    const int wn  = wid & 3;                     // 0..3 : 32-col slab
    const int m0  = blockIdx.y * GBM;
    const int n0  = blockIdx.x * GBN;

    float acc[4][4][4];
#pragma unroll
    for (int i = 0; i < 4; i++)
#pragma unroll
        for (int j = 0; j < 4; j++)
#pragma unroll
            for (int r = 0; r < 4; r++) acc[i][j][r] = 0.0f;

    // Load 384 rows x 8 int4 per stage: 3072 slots / 512 threads = 6 each.
    auto issue = [&](int stage, int ck) {
        const __half* Ag = A  + (size_t)m0 * K + ck * BKH;
        const __half* Bg = Bw + (size_t)n0 * K + ck * BKH;
        const uint32_t dst = sb + stage * STAGE_BYTES;
#pragma unroll
        for (int i = 0; i < 6; i++) {
            int idx = tid + i * 512;             // 0..3071
            int row = idx >> 3;                  // 0..383
            int c   = idx & 7;
            uint32_t so = (uint32_t)(row * SSTRH + c * 8) * 2;
            const __half* src = (row < GBM)
                ? Ag + (size_t)row * K + c * 8
                : Bg + (size_t)(row - GBM) * K + c * 8;
            cp_async16(dst + so, src);
        }
        CP_COMMIT();
    };

    const int NCH = K / BKH;                     // 16
    issue(0, 0);

    const int a_row = lid & 15;
    const int a_col = (lid >> 4) * 8;
    const int b_row = (lid & 7) + ((lid >> 4) & 1) * 8;
    const int b_col = ((lid >> 3) & 1) * 8;

    for (int ck = 0; ck < NCH; ck++) {
        if (ck + 1 < NCH) { issue((ck + 1) & 1, ck + 1); CP_WAIT1(); }
        else              { CP_WAIT0(); }
        __syncthreads();

        const uint32_t buf = sb + (ck & 1) * STAGE_BYTES;

#pragma unroll
        for (int kk = 0; kk < 4; kk++) {
            const int koff = kk * 16;
            uint32_t af[4][4], bf[4][2];
#pragma unroll
            for (int mt = 0; mt < 4; mt++) {
                uint32_t ad = buf + 2 * (uint32_t)((wm * 64 + mt * 16 + a_row) * SSTRH
                                                   + koff + a_col);
                ldsm_x4(af[mt][0], af[mt][1], af[mt][2], af[mt][3], ad);
            }
#pragma unroll
            for (int p = 0; p < 2; p++) {
                uint32_t bd = buf + 2 * (uint32_t)((GBM + wn * 32 + p * 16 + b_row) * SSTRH
                                                   + koff + b_col);
                ldsm_x4(bf[2 * p][0], bf[2 * p][1], bf[2 * p + 1][0],
                        bf[2 * p + 1][1], bd);
            }
#pragma unroll
            for (int mt = 0; mt < 4; mt++)
#pragma unroll
                for (int nt = 0; nt < 4; nt++)
                    mma_f16_16n8k16(acc[mt][nt], af[mt], bf[nt]);
        }
        __syncthreads();   // all warps done with buf before next issue overwrites
    }

#pragma unroll
    for (int mt = 0; mt < 4; mt++) {
#pragma unroll
        for (int nt = 0; nt < 4; nt++) {
            int row = m0 + wm * 64 + mt * 16 + gid;
            int col = n0 + wn * 32 + nt * 8 + 2 * tig;
            if (sizeof(OutT) == 4) {
                float* Cf = (float*)C;
                *(float2*)&Cf[(size_t)row * N + col] =
                    make_float2(acc[mt][nt][0] * scale, acc[mt][nt][1] * scale);
                *(float2*)&Cf[(size_t)(row + 8) * N + col] =
                    make_float2(acc[mt][nt][2] * scale, acc[mt][nt][3] * scale);
            } else {
                __half* Ch = (__half*)C;
                *(__half2*)&Ch[(size_t)row * N + col] =
                    __floats2half2_rn(acc[mt][nt][0] * scale, acc[mt][nt][1] * scale);
                *(__half2*)&Ch[(size_t)(row + 8) * N + col] =
                    __floats2half2_rn(acc[mt][nt][2] * scale, acc[mt][nt][3] * scale);
            }
        }
    }
}

// Fused QKV: grid (8, 32, 3)
__global__ __launch_bounds__(512)
void gemm_qkv_kernel(const __half* __restrict__ xh,
                     const __half* __restrict__ whBase,
                     __half* __restrict__ qh, __half* __restrict__ kh,
                     __half* __restrict__ vh) {
    extern __shared__ char smemc[];
    const int slot = blockIdx.z;
    const __half* Bw = whBase + (size_t)slot * DMODEL * DMODEL;
    __half* C = (slot == 0) ? qh : (slot == 1) ? kh : vh;
    const float scale = (slot == 0) ? 0.125f : 1.0f;
    gemm_body<__half>(xh, Bw, C, scale, smemc);
}

__global__ __launch_bounds__(512)
void gemm_out_kernel(const __half* __restrict__ A,
                     const __half* __restrict__ Bw,
                     float* __restrict__ C) {
    extern __shared__ char smemc[];
    gemm_body<float>(A, Bw, C, 1.0f, smemc);
}

// ===========================================================================
// Tensor-core flash attention (round-9 form: V^T precomputed, non-trans
// ldmatrix everywhere — trans ldmatrix measured 200+us slower on sm_103a).
// grid (SEQ/128, NHEADS, BATCH), 128 threads = 4 warps; warp: 32 q-rows.
// ===========================================================================
#define FBKV 64
#define FSTR 72

__global__ __launch_bounds__(128)
void flash_tc_kernel(const __half* __restrict__ Qh,
                     const __half* __restrict__ Kh,
                     const __half* __restrict__ Vt,
                     const int*   __restrict__ am,
                     __half* __restrict__ O) {
    __shared__ __half Ks[2][FBKV * FSTR];
    __shared__ __half Vs[2][FBKV * FSTR];
    __shared__ float  Ms[2][FBKV];

    const int tid = threadIdx.x;
    const int wid = tid >> 5;
    const int lid = tid & 31;
    const int gid = lid >> 2;
    const int tig = lid & 3;
    const int q0  = blockIdx.x * 128;
    const int h   = blockIdx.y;
    const int b   = blockIdx.z;
    const int qw0 = q0 + wid * 32;

    const uint32_t ksa = smem_u32(Ks);
    const uint32_t vsa = smem_u32(Vs);
    const int b_row = (lid & 7) + ((lid >> 4) & 1) * 8;
    const int b_col = ((lid >> 3) & 1) * 8;

    uint32_t qf[2][4][4];
#pragma unroll
    for (int mt = 0; mt < 2; mt++)
#pragma unroll
        for (int kt = 0; kt < 4; kt++) {
            const __half* base = Qh + ((size_t)(b * SEQ) + qw0 + mt * 16 + gid) * DMODEL
                                    + h * 64 + kt * 16 + 2 * tig;
            qf[mt][kt][0] = *(const uint32_t*)base;
            qf[mt][kt][1] = *(const uint32_t*)(base + 8 * DMODEL);
            qf[mt][kt][2] = *(const uint32_t*)(base + 8);
            qf[mt][kt][3] = *(const uint32_t*)(base + 8 * DMODEL + 8);
        }

    float o[2][8][4];
#pragma unroll
    for (int mt = 0; mt < 2; mt++)
#pragma unroll
        for (int nt = 0; nt < 8; nt++)
#pragma unroll
            for (int r = 0; r < 4; r++) o[mt][nt][r] = 0.0f;
    float m_run[2][2] = { { -1e30f, -1e30f }, { -1e30f, -1e30f } };
    float lp[2][2]    = { { 0.0f, 0.0f }, { 0.0f, 0.0f } };

    const int nkb = (q0 + 128) / FBKV;

    auto issue = [&](int buf, int kb) {
        const int kv0 = kb * FBKV;
#pragma unroll
        for (int i = 0; i < 4; i++) {
            int idx = tid + i * 128;
            int row = idx >> 3;
            int c   = idx & 7;
            uint32_t so = (uint32_t)(buf * FBKV * FSTR + row * FSTR + c * 8) * 2;
            cp_async16(ksa + so,
                       Kh + ((size_t)(b * SEQ) + kv0 + row) * DMODEL + h * 64 + c * 8);
            cp_async16(vsa + so,
                       Vt + ((size_t)((b * 16 + h) * 64) + row) * SEQ + kv0 + c * 8);
        }
        CP_COMMIT();
        if (tid < FBKV)
            Ms[buf][tid] = am[b * SEQ + kv0 + tid] ? 0.0f : -1e30f;
    };

    issue(0, 0);

    for (int kb = 0; kb < nkb; kb++) {
        if (kb + 1 < nkb) { issue((kb + 1) & 1, kb + 1); CP_WAIT1(); }
        else              { CP_WAIT0(); }
        __syncthreads();

        const int buf = kb & 1;
        const int kv0 = kb * FBKV;
        const uint32_t kbase = ksa + (uint32_t)(buf * FBKV * FSTR) * 2;
        const uint32_t vbase = vsa + (uint32_t)(buf * FBKV * FSTR) * 2;

        if (kv0 <= qw0 + 31) {
            // ---- S = Q K^T ----
            float s[2][8][4];
#pragma unroll
            for (int mt = 0; mt < 2; mt++)
#pragma unroll
                for (int nt = 0; nt < 8; nt++)
#pragma unroll
                    for (int r = 0; r < 4; r++) s[mt][nt][r] = 0.0f;

#pragma unroll
            for (int kt = 0; kt < 4; kt++) {
                uint32_t bf[8][2];
#pragma unroll
                for (int p = 0; p < 4; p++) {
                    uint32_t ad = kbase + 2 * (uint32_t)((p * 16 + b_row) * FSTR
                                                         + kt * 16 + b_col);
                    ldsm_x4(bf[2 * p][0], bf[2 * p][1], bf[2 * p + 1][0],
                            bf[2 * p + 1][1], ad);
                }
#pragma unroll
                for (int mt = 0; mt < 2; mt++)
#pragma unroll
                    for (int nt = 0; nt < 8; nt++)
                        mma_f16_16n8k16(s[mt][nt], qf[mt][kt], bf[nt]);
            }

            // ---- mask + online softmax ----
#pragma unroll
            for (int mt = 0; mt < 2; mt++)
#pragma unroll
                for (int r = 0; r < 2; r++) {
                    const int row = qw0 + mt * 16 + gid + r * 8;
                    float mx = -1e30f;
#pragma unroll
                    for (int nt = 0; nt < 8; nt++)
#pragma unroll
                        for (int c = 0; c < 2; c++) {
                            const int jl = nt * 8 + 2 * tig + c;
                            float v = s[mt][nt][r * 2 + c] + Ms[buf][jl];
                            if (kv0 + jl > row) v = -1e30f;
                            s[mt][nt][r * 2 + c] = v;
                            mx = fmaxf(mx, v);
                        }
                    mx = fmaxf(mx, __shfl_xor_sync(0xffffffff, mx, 1));
                    mx = fmaxf(mx, __shfl_xor_sync(0xffffffff, mx, 2));
                    const float mnew = fmaxf(m_run[mt][r], mx);
                    const float corr = __expf(m_run[mt][r] - mnew);
                    m_run[mt][r] = mnew;
                    lp[mt][r] *= corr;
                    float ls = 0.0f;
#pragma unroll
                    for (int nt = 0; nt < 8; nt++) {
                        o[mt][nt][r * 2]     *= corr;
                        o[mt][nt][r * 2 + 1] *= corr;
                        float p0 = __expf(s[mt][nt][r * 2]     - mnew);
                        float p1 = __expf(s[mt][nt][r * 2 + 1] - mnew);
                        s[mt][nt][r * 2]     = p0;
                        s[mt][nt][r * 2 + 1] = p1;
                        ls += p0 + p1;
                    }
                    lp[mt][r] += ls;
                }

            // ---- O += P V ----
#pragma unroll
            for (int kt = 0; kt < 4; kt++) {
                uint32_t bfv[8][2];
#pragma unroll
                for (int p = 0; p < 4; p++) {
                    uint32_t ad = vbase + 2 * (uint32_t)((p * 16 + b_row) * FSTR
                                                         + kt * 16 + b_col);
                    ldsm_x4(bfv[2 * p][0], bfv[2 * p][1], bfv[2 * p + 1][0],
                            bfv[2 * p + 1][1], ad);
                }
#pragma unroll
                for (int mt = 0; mt < 2; mt++) {
                    uint32_t pa[4];
                    pa[0] = h2u(s[mt][2 * kt][0],     s[mt][2 * kt][1]);
                    pa[1] = h2u(s[mt][2 * kt][2],     s[mt][2 * kt][3]);
                    pa[2] = h2u(s[mt][2 * kt + 1][0], s[mt][2 * kt + 1][1]);
                    pa[3] = h2u(s[mt][2 * kt + 1][2], s[mt][2 * kt + 1][3]);
#pragma unroll
                    for (int nt = 0; nt < 8; nt++)
                        mma_f16_16n8k16(o[mt][nt], pa, bfv[nt]);
                }
            }
        }
        __syncthreads();
    }

    // ---- epilogue ----
#pragma unroll
    for (int mt = 0; mt < 2; mt++)
#pragma unroll
        for (int r = 0; r < 2; r++) {
            float l = lp[mt][r];
            l += __shfl_xor_sync(0xffffffff, l, 1);
            l += __shfl_xor_sync(0xffffffff, l, 2);
            const float inv = 1.0f / l;
            const int row = qw0 + mt * 16 + gid + r * 8;
            __half* orow = O + ((size_t)(b * SEQ) + row) * DMODEL + h * 64;
#pragma unroll
            for (int nt = 0; nt < 8; nt++)
                *(__half2*)&orow[nt * 8 + 2 * tig] =
                    __floats2half2_rn(o[mt][nt][r * 2] * inv,
                                      o[mt][nt][r * 2 + 1] * inv);
        }
}

// ---------------------------------------------------------------------------
extern "C" void kernel_launch(void* const* d_in, const int* in_sizes, int n_in,
                              void* d_out, int out_size) {
    const float* x  = (const float*)d_in[0];
    const int*   am = (const int*)  d_in[1];
    float* out = (float*)d_out;

    __half *xh, *qh, *kh, *vh, *vt, *oh, *wh;
    cudaGetSymbolAddress((void**)&xh, g_xh);
    cudaGetSymbolAddress((void**)&qh, g_qh);
    cudaGetSymbolAddress((void**)&kh, g_kh);
    cudaGetSymbolAddress((void**)&vh, g_vh);
    cudaGetSymbolAddress((void**)&vt, g_vt);
    cudaGetSymbolAddress((void**)&oh, g_oh);
    cudaGetSymbolAddress((void**)&wh, g_wh);

    cudaFuncSetAttribute(gemm_qkv_kernel,
                         cudaFuncAttributeMaxDynamicSharedMemorySize, SMEM_GEMM);
    cudaFuncSetAttribute(gemm_out_kernel,
                         cudaFuncAttributeMaxDynamicSharedMemorySize, SMEM_GEMM);

    {
        int n4 = MROWS * DMODEL / 4;
        f2h_kernel<<<(n4 + 255) / 256, 256>>>(x, xh, n4);
        int w4 = DMODEL * DMODEL / 4;
        dim3 wg((w4 + 255) / 256, 4);
        f2h4_kernel<<<wg, 256>>>((const float*)d_in[2], (const float*)d_in[3],
                                 (const float*)d_in[4], (const float*)d_in[5],
                                 wh, w4);
    }

    dim3 gq(DMODEL / GBN, MROWS / GBM, 3);    // (8, 32, 3)
    gemm_qkv_kernel<<<gq, 512, SMEM_GEMM>>>(xh, wh, qh, kh, vh);

    dim3 tg(SEQ / 64, NHEADS, BATCH);
    vtrans_kernel<<<tg, 256>>>(vh, vt);

    dim3 fg(SEQ / 128, NHEADS, BATCH);        // (16, 16, 4)
    flash_tc_kernel<<<fg, 128>>>(qh, kh, vt, am, oh);

    dim3 gg(DMODEL / GBN, MROWS / GBM);       // (8, 32)
    gemm_out_kernel<<<gg, 512, SMEM_GEMM>>>(
        oh, wh + 3 * (size_t)DMODEL * DMODEL, out);
}

// round 13
// speedup vs baseline: 1.4767x; 1.0382x over previous
#include <cuda_runtime.h>
#include <cuda_fp16.h>
#include <cstdint>
#include <math.h>

#define BATCH  4
#define SEQ    2048
#define DMODEL 1024
#define NHEADS 16
#define HDIM   64
#define MROWS  (BATCH * SEQ)

// Scratch (allocation-free)
__device__ __half g_xh[MROWS * DMODEL];
__device__ __half g_qh[MROWS * DMODEL];
__device__ __half g_kh[MROWS * DMODEL];
__device__ __half g_vt[MROWS * DMODEL];       // V^T per (b,h): [(b*16+h)*64+d][s]
__device__ __half g_oh[MROWS * DMODEL];
__device__ __half g_wh[4][DMODEL * DMODEL];   // wq, wk, wv, wo as fp16

// ---------------------------------------------------------------------------
// Helpers
// ---------------------------------------------------------------------------
__device__ __forceinline__ uint32_t smem_u32(const void* p) {
    uint32_t a;
    asm("{ .reg .u64 t; cvta.to.shared.u64 t, %1; cvt.u32.u64 %0, t; }"
        : "=r"(a) : "l"(p));
    return a;
}

__device__ __forceinline__ void cp_async16(uint32_t dst, const void* src) {
    asm volatile("cp.async.cg.shared.global [%0], [%1], 16;"
                 :: "r"(dst), "l"(src));
}
#define CP_COMMIT() asm volatile("cp.async.commit_group;" ::: "memory")
#define CP_WAIT1()  asm volatile("cp.async.wait_group 1;" ::: "memory")
#define CP_WAIT0()  asm volatile("cp.async.wait_group 0;" ::: "memory")

__device__ __forceinline__ void mma_f16_16n8k16(float* c, const uint32_t* a,
                                                const uint32_t* b) {
    asm volatile(
        "mma.sync.aligned.m16n8k16.row.col.f32.f16.f16.f32 "
        "{%0,%1,%2,%3}, {%4,%5,%6,%7}, {%8,%9}, {%0,%1,%2,%3};"
        : "+f"(c[0]), "+f"(c[1]), "+f"(c[2]), "+f"(c[3])
        : "r"(a[0]), "r"(a[1]), "r"(a[2]), "r"(a[3]), "r"(b[0]), "r"(b[1]));
}

__device__ __forceinline__ void ldsm_x4(uint32_t& r0, uint32_t& r1,
                                        uint32_t& r2, uint32_t& r3,
                                        uint32_t addr) {
    asm volatile("ldmatrix.sync.aligned.m8n8.x4.shared.b16 {%0,%1,%2,%3}, [%4];"
                 : "=r"(r0), "=r"(r1), "=r"(r2), "=r"(r3) : "r"(addr));
}

__device__ __forceinline__ uint32_t h2u(float a, float b) {
    __half2 h = __floats2half2_rn(a, b);
    return *(uint32_t*)&h;
}

// ---------------------------------------------------------------------------
// Fused fp32 -> fp16 conversion: slice 0 = x (8M elems), 1..4 = weights (1M).
// ---------------------------------------------------------------------------
__global__ void f2h_all_kernel(const float* __restrict__ x,
                               const float* __restrict__ w0,
                               const float* __restrict__ w1,
                               const float* __restrict__ w2,
                               const float* __restrict__ w3,
                               __half* __restrict__ xh,
                               __half* __restrict__ wh) {
    const int j = blockIdx.y;
    const float* s;
    __half* d;
    int n4;
    if (j == 0) { s = x; d = xh; n4 = MROWS * DMODEL / 4; }
    else {
        s = (j == 1) ? w0 : (j == 2) ? w1 : (j == 3) ? w2 : w3;
        d = wh + (size_t)(j - 1) * DMODEL * DMODEL;
        n4 = DMODEL * DMODEL / 4;
    }
    int i = blockIdx.x * blockDim.x + threadIdx.x;
    if (i < n4) {
        float4 v = ((const float4*)s)[i];
        ((__half2*)d)[2 * i]     = __floats2half2_rn(v.x, v.y);
        ((__half2*)d)[2 * i + 1] = __floats2half2_rn(v.z, v.w);
    }
}

// ===========================================================================
// fp16 tensor-core GEMM:  C[M,1024] = scale * (A(f16) @ B(f16)^T)
// CTA 128x128, BK=64, 8 warps, warp 64x32, 3-stage cp.async, ldmatrix loads.
// vt_mode: write the output tile TRANSPOSED per (b,h) into vt layout
//          [(b*16+h)*64+d][s] via an smem-staged transpose (fuses the old
//          vtrans kernel into the V-projection epilogue).
// ===========================================================================
#define GBM 128
#define GBN 128
#define BKH 64
#define SSTRH 72
#define STAGE_BYTES (2 * 128 * SSTRH * 2)        // 36864
#define SMEM_GEMM   (3 * STAGE_BYTES)            // 110592

template <typename OutT>
__device__ __forceinline__ void gemm_body(const __half* __restrict__ A,
                                          const __half* __restrict__ Bw,
                                          OutT* __restrict__ C, float scale,
                                          char* smemc, int vt_mode) {
    const uint32_t sb = smem_u32(smemc);
    const int K = DMODEL, N = DMODEL;
    const int tid = threadIdx.x;
    const int wid = tid >> 5;
    const int lid = tid & 31;
    const int gid = lid >> 2;
    const int tig = lid & 3;
    const int wm  = wid >> 2;
    const int wn  = wid & 3;
    const int m0  = blockIdx.y * GBM;
    const int n0  = blockIdx.x * GBN;

    float acc[4][4][4];
#pragma unroll
    for (int i = 0; i < 4; i++)
#pragma unroll
        for (int j = 0; j < 4; j++)
#pragma unroll
            for (int r = 0; r < 4; r++) acc[i][j][r] = 0.0f;

    auto issue = [&](int stage, int ck) {
        const __half* Ag = A  + (size_t)m0 * K + ck * BKH;
        const __half* Bg = Bw + (size_t)n0 * K + ck * BKH;
        const uint32_t da = sb + stage * STAGE_BYTES;
        const uint32_t db = da + 128 * SSTRH * 2;
#pragma unroll
        for (int i = 0; i < 4; i++) {
            int idx = tid + i * 256;
            int row = idx >> 3;
            int c   = idx & 7;
            uint32_t so = (uint32_t)(row * SSTRH + c * 8) * 2;
            cp_async16(da + so, Ag + (size_t)row * K + c * 8);
            cp_async16(db + so, Bg + (size_t)row * K + c * 8);
        }
        CP_COMMIT();
    };

    const int NCH = K / BKH;                     // 16
    issue(0, 0);
    issue(1, 1);

    const int a_row = lid & 15;
    const int a_col = (lid >> 4) * 8;
    const int b_row = (lid & 7) + ((lid >> 4) & 1) * 8;
    const int b_col = ((lid >> 3) & 1) * 8;

    for (int ck = 0; ck < NCH; ck++) {
        if (ck + 1 < NCH) { CP_WAIT1(); } else { CP_WAIT0(); }
        __syncthreads();
        if (ck + 2 < NCH) issue((ck + 2) % 3, ck + 2);

        const uint32_t bufA = sb + (ck % 3) * STAGE_BYTES;
        const uint32_t bufB = bufA + 128 * SSTRH * 2;

#pragma unroll
        for (int kk = 0; kk < 4; kk++) {
            const int koff = kk * 16;
            uint32_t af[4][4], bf[4][2];
#pragma unroll
            for (int mt = 0; mt < 4; mt++) {
                uint32_t ad = bufA + 2 * (uint32_t)((wm * 64 + mt * 16 + a_row) * SSTRH
                                                    + koff + a_col);
                ldsm_x4(af[mt][0], af[mt][1], af[mt][2], af[mt][3], ad);
            }
#pragma unroll
            for (int p = 0; p < 2; p++) {
                uint32_t bd = bufB + 2 * (uint32_t)((wn * 32 + p * 16 + b_row) * SSTRH
                                                    + koff + b_col);
                ldsm_x4(bf[2 * p][0], bf[2 * p][1], bf[2 * p + 1][0],
                        bf[2 * p + 1][1], bd);
            }
#pragma unroll
            for (int mt = 0; mt < 4; mt++)
#pragma unroll
                for (int nt = 0; nt < 4; nt++)
                    mma_f16_16n8k16(acc[mt][nt], af[mt], bf[nt]);
        }
    }

    if (!vt_mode) {
#pragma unroll
        for (int mt = 0; mt < 4; mt++) {
#pragma unroll
            for (int nt = 0; nt < 4; nt++) {
                int row = m0 + wm * 64 + mt * 16 + gid;
                int col = n0 + wn * 32 + nt * 8 + 2 * tig;
                if (sizeof(OutT) == 4) {
                    float* Cf = (float*)C;
                    *(float2*)&Cf[(size_t)row * N + col] =
                        make_float2(acc[mt][nt][0] * scale, acc[mt][nt][1] * scale);
                    *(float2*)&Cf[(size_t)(row + 8) * N + col] =
                        make_float2(acc[mt][nt][2] * scale, acc[mt][nt][3] * scale);
                } else {
                    __half* Ch = (__half*)C;
                    *(__half2*)&Ch[(size_t)row * N + col] =
                        __floats2half2_rn(acc[mt][nt][0] * scale, acc[mt][nt][1] * scale);
                    *(__half2*)&Ch[(size_t)(row + 8) * N + col] =
                        __floats2half2_rn(acc[mt][nt][2] * scale, acc[mt][nt][3] * scale);
                }
            }
        }
    } else {
        // V projection: stage tile to smem (padded stride 130), write transposed.
        __syncthreads();                         // pipeline buffers now dead
        __half (*sm)[130] = (__half(*)[130])smemc;
#pragma unroll
        for (int mt = 0; mt < 4; mt++) {
#pragma unroll
            for (int nt = 0; nt < 4; nt++) {
                int r0 = wm * 64 + mt * 16 + gid;
                int c0 = wn * 32 + nt * 8 + 2 * tig;
                *(__half2*)&sm[r0][c0] =
                    __floats2half2_rn(acc[mt][nt][0], acc[mt][nt][1]);
                *(__half2*)&sm[r0 + 8][c0] =
                    __floats2half2_rn(acc[mt][nt][2], acc[mt][nt][3]);
            }
        }
        __syncthreads();
        const int b  = m0 >> 11;                 // m0 / 2048
        const int s0 = m0 & 2047;
        const int d  = tid >> 1;                 // 0..127 local dim
        const int hs = (tid & 1) * 64;           // s half-range
        const int hh = (n0 + d) >> 6;            // global head
        const int dl = (n0 + d) & 63;
        __half* dst = (__half*)C +
            ((size_t)((b * 16 + hh) * 64 + dl)) * SEQ + s0 + hs;
#pragma unroll
        for (int i = 0; i < 8; i++) {
            uint32_t w[4];
#pragma unroll
            for (int j = 0; j < 4; j++) {
                __half2 p = __halves2half2(sm[hs + i * 8 + 2 * j][d],
                                           sm[hs + i * 8 + 2 * j + 1][d]);
                w[j] = *(uint32_t*)&p;
            }
            *(int4*)&dst[i * 8] = make_int4(w[0], w[1], w[2], w[3]);
        }
    }
}

// Fused QKV: grid (8, 64, 3). Slot 2 writes V transposed into vt.
__global__ __launch_bounds__(256)
void gemm_qkv_kernel(const __half* __restrict__ xh,
                     const __half* __restrict__ whBase,
                     __half* __restrict__ qh, __half* __restrict__ kh,
                     __half* __restrict__ vt) {
    extern __shared__ char smemc[];
    const int slot = blockIdx.z;
    const __half* Bw = whBase + (size_t)slot * DMODEL * DMODEL;
    __half* C = (slot == 0) ? qh : (slot == 1) ? kh : vt;
    const float scale = (slot == 0) ? 0.125f : 1.0f;
    gemm_body<__half>(xh, Bw, C, scale, smemc, slot == 2);
}

__global__ __launch_bounds__(256)
void gemm_out_kernel(const __half* __restrict__ A,
                     const __half* __restrict__ Bw,
                     float* __restrict__ C) {
    extern __shared__ char smemc[];
    gemm_body<float>(A, Bw, C, 1.0f, smemc, 0);
}

// ===========================================================================
// Tensor-core flash attention (round-9 form; V^T consumed from vt).
// grid (SEQ/128, NHEADS, BATCH), 128 threads = 4 warps; warp: 32 q-rows.
// ===========================================================================
#define FBKV 64
#define FSTR 72

__global__ __launch_bounds__(128)
void flash_tc_kernel(const __half* __restrict__ Qh,
                     const __half* __restrict__ Kh,
                     const __half* __restrict__ Vt,
                     const int*   __restrict__ am,
                     __half* __restrict__ O) {
    __shared__ __half Ks[2][FBKV * FSTR];
    __shared__ __half Vs[2][FBKV * FSTR];
    __shared__ float  Ms[2][FBKV];

    const int tid = threadIdx.x;
    const int wid = tid >> 5;
    const int lid = tid & 31;
    const int gid = lid >> 2;
    const int tig = lid & 3;
    const int q0  = blockIdx.x * 128;
    const int h   = blockIdx.y;
    const int b   = blockIdx.z;
    const int qw0 = q0 + wid * 32;

    const uint32_t ksa = smem_u32(Ks);
    const uint32_t vsa = smem_u32(Vs);
    const int b_row = (lid & 7) + ((lid >> 4) & 1) * 8;
    const int b_col = ((lid >> 3) & 1) * 8;

    uint32_t qf[2][4][4];
#pragma unroll
    for (int mt = 0; mt < 2; mt++)
#pragma unroll
        for (int kt = 0; kt < 4; kt++) {
            const __half* base = Qh + ((size_t)(b * SEQ) + qw0 + mt * 16 + gid) * DMODEL
                                    + h * 64 + kt * 16 + 2 * tig;
            qf[mt][kt][0] = *(const uint32_t*)base;
            qf[mt][kt][1] = *(const uint32_t*)(base + 8 * DMODEL);
            qf[mt][kt][2] = *(const uint32_t*)(base + 8);
            qf[mt][kt][3] = *(const uint32_t*)(base + 8 * DMODEL + 8);
        }

    float o[2][8][4];
#pragma unroll
    for (int mt = 0; mt < 2; mt++)
#pragma unroll
        for (int nt = 0; nt < 8; nt++)
#pragma unroll
            for (int r = 0; r < 4; r++) o[mt][nt][r] = 0.0f;
    float m_run[2][2] = { { -1e30f, -1e30f }, { -1e30f, -1e30f } };
    float lp[2][2]    = { { 0.0f, 0.0f }, { 0.0f, 0.0f } };

    const int nkb = (q0 + 128) / FBKV;

    auto issue = [&](int buf, int kb) {
        const int kv0 = kb * FBKV;
#pragma unroll
        for (int i = 0; i < 4; i++) {
            int idx = tid + i * 128;
            int row = idx >> 3;
            int c   = idx & 7;
            uint32_t so = (uint32_t)(buf * FBKV * FSTR + row * FSTR + c * 8) * 2;
            cp_async16(ksa + so,
                       Kh + ((size_t)(b * SEQ) + kv0 + row) * DMODEL + h * 64 + c * 8);
            cp_async16(vsa + so,
                       Vt + ((size_t)((b * 16 + h) * 64) + row) * SEQ + kv0 + c * 8);
        }
        CP_COMMIT();
        if (tid < FBKV)
            Ms[buf][tid] = am[b * SEQ + kv0 + tid] ? 0.0f : -1e30f;
    };

    issue(0, 0);

    for (int kb = 0; kb < nkb; kb++) {
        if (kb + 1 < nkb) { issue((kb + 1) & 1, kb + 1); CP_WAIT1(); }
        else              { CP_WAIT0(); }
        __syncthreads();

        const int buf = kb & 1;
        const int kv0 = kb * FBKV;
        const uint32_t kbase = ksa + (uint32_t)(buf * FBKV * FSTR) * 2;
        const uint32_t vbase = vsa + (uint32_t)(buf * FBKV * FSTR) * 2;

        if (kv0 <= qw0 + 31) {
            // ---- S = Q K^T ----
            float s[2][8][4];
#pragma unroll
            for (int mt = 0; mt < 2; mt++)
#pragma unroll
                for (int nt = 0; nt < 8; nt++)
#pragma unroll
                    for (int r = 0; r < 4; r++) s[mt][nt][r] = 0.0f;

#pragma unroll
            for (int kt = 0; kt < 4; kt++) {
                uint32_t bf[8][2];
#pragma unroll
                for (int p = 0; p < 4; p++) {
                    uint32_t ad = kbase + 2 * (uint32_t)((p * 16 + b_row) * FSTR
                                                         + kt * 16 + b_col);
                    ldsm_x4(bf[2 * p][0], bf[2 * p][1], bf[2 * p + 1][0],
                            bf[2 * p + 1][1], ad);
                }
#pragma unroll
                for (int mt = 0; mt < 2; mt++)
#pragma unroll
                    for (int nt = 0; nt < 8; nt++)
                        mma_f16_16n8k16(s[mt][nt], qf[mt][kt], bf[nt]);
            }

            // ---- mask + online softmax ----
#pragma unroll
            for (int mt = 0; mt < 2; mt++)
#pragma unroll
                for (int r = 0; r < 2; r++) {
                    const int row = qw0 + mt * 16 + gid + r * 8;
                    float mx = -1e30f;
#pragma unroll
                    for (int nt = 0; nt < 8; nt++)
#pragma unroll
                        for (int c = 0; c < 2; c++) {
                            const int jl = nt * 8 + 2 * tig + c;
                            float v = s[mt][nt][r * 2 + c] + Ms[buf][jl];
                            if (kv0 + jl > row) v = -1e30f;
                            s[mt][nt][r * 2 + c] = v;
                            mx = fmaxf(mx, v);
                        }
                    mx = fmaxf(mx, __shfl_xor_sync(0xffffffff, mx, 1));
                    mx = fmaxf(mx, __shfl_xor_sync(0xffffffff, mx, 2));
                    const float mnew = fmaxf(m_run[mt][r], mx);
                    const float corr = __expf(m_run[mt][r] - mnew);
                    m_run[mt][r] = mnew;
                    lp[mt][r] *= corr;
                    float ls = 0.0f;
#pragma unroll
                    for (int nt = 0; nt < 8; nt++) {
                        o[mt][nt][r * 2]     *= corr;
                        o[mt][nt][r * 2 + 1] *= corr;
                        float p0 = __expf(s[mt][nt][r * 2]     - mnew);
                        float p1 = __expf(s[mt][nt][r * 2 + 1] - mnew);
                        s[mt][nt][r * 2]     = p0;
                        s[mt][nt][r * 2 + 1] = p1;
                        ls += p0 + p1;
                    }
                    lp[mt][r] += ls;
                }

            // ---- O += P V ----
#pragma unroll
            for (int kt = 0; kt < 4; kt++) {
                uint32_t bfv[8][2];
#pragma unroll
                for (int p = 0; p < 4; p++) {
                    uint32_t ad = vbase + 2 * (uint32_t)((p * 16 + b_row) * FSTR
                                                         + kt * 16 + b_col);
                    ldsm_x4(bfv[2 * p][0], bfv[2 * p][1], bfv[2 * p + 1][0],
                            bfv[2 * p + 1][1], ad);
                }
#pragma unroll
                for (int mt = 0; mt < 2; mt++) {
                    uint32_t pa[4];
                    pa[0] = h2u(s[mt][2 * kt][0],     s[mt][2 * kt][1]);
                    pa[1] = h2u(s[mt][2 * kt][2],     s[mt][2 * kt][3]);
                    pa[2] = h2u(s[mt][2 * kt + 1][0], s[mt][2 * kt + 1][1]);
                    pa[3] = h2u(s[mt][2 * kt + 1][2], s[mt][2 * kt + 1][3]);
#pragma unroll
                    for (int nt = 0; nt < 8; nt++)
                        mma_f16_16n8k16(o[mt][nt], pa, bfv[nt]);
                }
            }
        }
        __syncthreads();
    }

    // ---- epilogue ----
#pragma unroll
    for (int mt = 0; mt < 2; mt++)
#pragma unroll
        for (int r = 0; r < 2; r++) {
            float l = lp[mt][r];
            l += __shfl_xor_sync(0xffffffff, l, 1);
            l += __shfl_xor_sync(0xffffffff, l, 2);
            const float inv = 1.0f / l;
            const int row = qw0 + mt * 16 + gid + r * 8;
            __half* orow = O + ((size_t)(b * SEQ) + row) * DMODEL + h * 64;
#pragma unroll
            for (int nt = 0; nt < 8; nt++)
                *(__half2*)&orow[nt * 8 + 2 * tig] =
                    __floats2half2_rn(o[mt][nt][r * 2] * inv,
                                      o[mt][nt][r * 2 + 1] * inv);
        }
}

// ---------------------------------------------------------------------------
extern "C" void kernel_launch(void* const* d_in, const int* in_sizes, int n_in,
                              void* d_out, int out_size) {
    const float* x  = (const float*)d_in[0];
    const int*   am = (const int*)  d_in[1];
    float* out = (float*)d_out;

    __half *xh, *qh, *kh, *vt, *oh, *wh;
    cudaGetSymbolAddress((void**)&xh, g_xh);
    cudaGetSymbolAddress((void**)&qh, g_qh);
    cudaGetSymbolAddress((void**)&kh, g_kh);
    cudaGetSymbolAddress((void**)&vt, g_vt);
    cudaGetSymbolAddress((void**)&oh, g_oh);
    cudaGetSymbolAddress((void**)&wh, g_wh);

    cudaFuncSetAttribute(gemm_qkv_kernel,
                         cudaFuncAttributeMaxDynamicSharedMemorySize, SMEM_GEMM);
    cudaFuncSetAttribute(gemm_out_kernel,
                         cudaFuncAttributeMaxDynamicSharedMemorySize, SMEM_GEMM);

    {
        int nx4 = MROWS * DMODEL / 4;            // largest slice
        dim3 cg((nx4 + 255) / 256, 5);
        f2h_all_kernel<<<cg, 256>>>(x, (const float*)d_in[2], (const float*)d_in[3],
                                    (const float*)d_in[4], (const float*)d_in[5],
                                    xh, wh);
    }

    dim3 gq(DMODEL / GBN, MROWS / GBM, 3);    // (8, 64, 3)
    gemm_qkv_kernel<<<gq, 256, SMEM_GEMM>>>(xh, wh, qh, kh, vt);

    dim3 fg(SEQ / 128, NHEADS, BATCH);        // (16, 16, 4)
    flash_tc_kernel<<<fg, 128>>>(qh, kh, vt, am, oh);

    dim3 gg(DMODEL / GBN, MROWS / GBM);       // (8, 64)
    gemm_out_kernel<<<gg, 256, SMEM_GEMM>>>(
        oh, wh + 3 * (size_t)DMODEL * DMODEL, out);
}

// round 14
// speedup vs baseline: 1.6968x; 1.1490x over previous
#include <cuda_runtime.h>
#include <cuda_fp16.h>
#include <cstdint>
#include <math.h>

#define BATCH  4
#define SEQ    2048
#define DMODEL 1024
#define NHEADS 16
#define HDIM   64
#define MROWS  (BATCH * SEQ)

// Scratch (allocation-free)
__device__ __half g_xh[MROWS * DMODEL];
__device__ __half g_qh[MROWS * DMODEL];
__device__ __half g_kh[MROWS * DMODEL];
__device__ __half g_vh[MROWS * DMODEL];
__device__ __half g_vt[MROWS * DMODEL];       // V^T per (b,h): [(b*16+h)*64+d][s]
__device__ __half g_oh[MROWS * DMODEL];
__device__ __half g_wh[4][DMODEL * DMODEL];   // wq, wk, wv, wo as fp16

// ---------------------------------------------------------------------------
// Helpers
// ---------------------------------------------------------------------------
__device__ __forceinline__ uint32_t smem_u32(const void* p) {
    uint32_t a;
    asm("{ .reg .u64 t; cvta.to.shared.u64 t, %1; cvt.u32.u64 %0, t; }"
        : "=r"(a) : "l"(p));
    return a;
}

__device__ __forceinline__ void cp_async16(uint32_t dst, const void* src) {
    asm volatile("cp.async.cg.shared.global [%0], [%1], 16;"
                 :: "r"(dst), "l"(src));
}
#define CP_COMMIT() asm volatile("cp.async.commit_group;" ::: "memory")
#define CP_WAIT1()  asm volatile("cp.async.wait_group 1;" ::: "memory")
#define CP_WAIT0()  asm volatile("cp.async.wait_group 0;" ::: "memory")

__device__ __forceinline__ void mma_f16_16n8k16(float* c, const uint32_t* a,
                                                const uint32_t* b) {
    asm volatile(
        "mma.sync.aligned.m16n8k16.row.col.f32.f16.f16.f32 "
        "{%0,%1,%2,%3}, {%4,%5,%6,%7}, {%8,%9}, {%0,%1,%2,%3};"
        : "+f"(c[0]), "+f"(c[1]), "+f"(c[2]), "+f"(c[3])
        : "r"(a[0]), "r"(a[1]), "r"(a[2]), "r"(a[3]), "r"(b[0]), "r"(b[1]));
}

__device__ __forceinline__ void ldsm_x4(uint32_t& r0, uint32_t& r1,
                                        uint32_t& r2, uint32_t& r3,
                                        uint32_t addr) {
    asm volatile("ldmatrix.sync.aligned.m8n8.x4.shared.b16 {%0,%1,%2,%3}, [%4];"
                 : "=r"(r0), "=r"(r1), "=r"(r2), "=r"(r3) : "r"(addr));
}

__device__ __forceinline__ uint32_t h2u(float a, float b) {
    __half2 h = __floats2half2_rn(a, b);
    return *(uint32_t*)&h;
}

// 128B-row XOR swizzle (bits[6:4] ^= bits[9:7]) — conflict-free ldmatrix.
#define SWZ(x) ((x) ^ (((x) >> 3) & 0x70))

// ---------------------------------------------------------------------------
// Flat fused fp32 -> fp16 conversion: [0, 2M) = x, [2M, 3M) = 4 weights.
// ---------------------------------------------------------------------------
#define XF4  (MROWS * DMODEL / 4)                // 2097152
#define WF4  (DMODEL * DMODEL / 4)               // 262144
__global__ void f2h_flat_kernel(const float* __restrict__ x,
                                const float* __restrict__ w0,
                                const float* __restrict__ w1,
                                const float* __restrict__ w2,
                                const float* __restrict__ w3,
                                __half* __restrict__ xh,
                                __half* __restrict__ wh) {
    int i = blockIdx.x * blockDim.x + threadIdx.x;
    const float* s;
    __half* d;
    int o;
    if (i < XF4) { s = x; d = xh; o = i; }
    else {
        int r = i - XF4;
        int j = r >> 18;                         // / WF4
        o = r & (WF4 - 1);
        s = (j == 0) ? w0 : (j == 1) ? w1 : (j == 2) ? w2 : w3;
        d = wh + (size_t)j * DMODEL * DMODEL;
    }
    float4 v = ((const float4*)s)[o];
    ((__half2*)d)[2 * o]     = __floats2half2_rn(v.x, v.y);
    ((__half2*)d)[2 * o + 1] = __floats2half2_rn(v.z, v.w);
}

// ---------------------------------------------------------------------------
// V transpose: v[b*SEQ+s][h*64+d] -> vt[(b*16+h)*64+d][s]
// ---------------------------------------------------------------------------
__global__ __launch_bounds__(256)
void vtrans_kernel(const __half* __restrict__ v, __half* __restrict__ vt) {
    __shared__ __half t[64][72];
    const int tid = threadIdx.x;
    const int s0 = blockIdx.x * 64;
    const int h  = blockIdx.y;
    const int b  = blockIdx.z;
#pragma unroll
    for (int i = 0; i < 2; i++) {
        int idx = tid + i * 256, row = idx >> 3, c = idx & 7;
        *(int4*)&t[row][c * 8] =
            *(const int4*)&v[((size_t)(b * SEQ) + s0 + row) * DMODEL + h * 64 + c * 8];
    }
    __syncthreads();
#pragma unroll
    for (int i = 0; i < 2; i++) {
        int idx = tid + i * 256, d = idx >> 3, c = idx & 7;
        __half tmp[8];
#pragma unroll
        for (int k = 0; k < 8; k++) tmp[k] = t[c * 8 + k][d];
        *(int4*)&vt[((size_t)((b * 16 + h) * 64) + d) * SEQ + s0 + c * 8] =
            *(int4*)tmp;
    }
}

// ===========================================================================
// fp16 tensor-core GEMM:  C[M,1024] = scale * (A(f16) @ B(f16)^T)
// CTA 128x128, BK=64, 8 warps, warp 64x32, 3-stage cp.async, ldmatrix.
// XOR-swizzled 128B rows (no padding): stage 32KB, 3 stages = 96KB
// -> 2 CTAs/SM resident (vs 1 with padded stride-72 layout).
// ===========================================================================
#define GBM 128
#define GBN 128
#define BKH 64
#define TILE_BYTES  (128 * 128)                  // 16384 per matrix
#define STAGE_BYTES (2 * TILE_BYTES)             // 32768
#define SMEM_GEMM   (3 * STAGE_BYTES)            // 98304

template <typename OutT>
__device__ __forceinline__ void gemm_body(const __half* __restrict__ A,
                                          const __half* __restrict__ Bw,
                                          OutT* __restrict__ C, float scale,
                                          char* smemc) {
    const uint32_t sb = smem_u32(smemc);
    const int K = DMODEL, N = DMODEL;
    const int tid = threadIdx.x;
    const int wid = tid >> 5;
    const int lid = tid & 31;
    const int gid = lid >> 2;
    const int tig = lid & 3;
    const int wm  = wid >> 2;
    const int wn  = wid & 3;
    const int m0  = blockIdx.y * GBM;
    const int n0  = blockIdx.x * GBN;

    float acc[4][4][4];
#pragma unroll
    for (int i = 0; i < 4; i++)
#pragma unroll
        for (int j = 0; j < 4; j++)
#pragma unroll
            for (int r = 0; r < 4; r++) acc[i][j][r] = 0.0f;

    auto issue = [&](int stage, int ck) {
        const __half* Ag = A  + (size_t)m0 * K + ck * BKH;
        const __half* Bg = Bw + (size_t)n0 * K + ck * BKH;
        const uint32_t da = sb + stage * STAGE_BYTES;
        const uint32_t db = da + TILE_BYTES;
#pragma unroll
        for (int i = 0; i < 4; i++) {
            int idx = tid + i * 256;
            int row = idx >> 3;
            int c   = idx & 7;
            uint32_t so = SWZ((uint32_t)(row * 128 + c * 16));
            cp_async16(da + so, Ag + (size_t)row * K + c * 8);
            cp_async16(db + so, Bg + (size_t)row * K + c * 8);
        }
        CP_COMMIT();
    };

    const int NCH = K / BKH;                     // 16
    issue(0, 0);
    issue(1, 1);

    const int a_row = lid & 15;
    const int a_col = (lid >> 4) * 8;            // halfs
    const int b_row = (lid & 7) + ((lid >> 4) & 1) * 8;
    const int b_col = ((lid >> 3) & 1) * 8;      // halfs

    for (int ck = 0; ck < NCH; ck++) {
        if (ck + 1 < NCH) { CP_WAIT1(); } else { CP_WAIT0(); }
        __syncthreads();
        if (ck + 2 < NCH) issue((ck + 2) % 3, ck + 2);

        const uint32_t bufA = sb + (ck % 3) * STAGE_BYTES;
        const uint32_t bufB = bufA + TILE_BYTES;

#pragma unroll
        for (int kk = 0; kk < 4; kk++) {
            const int koff = kk * 16;            // halfs
            uint32_t af[4][4], bf[4][2];
#pragma unroll
            for (int mt = 0; mt < 4; mt++) {
                uint32_t byo = (uint32_t)((wm * 64 + mt * 16 + a_row) * 128
                                          + (koff + a_col) * 2);
                ldsm_x4(af[mt][0], af[mt][1], af[mt][2], af[mt][3],
                        bufA + SWZ(byo));
            }
#pragma unroll
            for (int p = 0; p < 2; p++) {
                uint32_t byo = (uint32_t)((wn * 32 + p * 16 + b_row) * 128
                                          + (koff + b_col) * 2);
                ldsm_x4(bf[2 * p][0], bf[2 * p][1], bf[2 * p + 1][0],
                        bf[2 * p + 1][1], bufB + SWZ(byo));
            }
#pragma unroll
            for (int mt = 0; mt < 4; mt++)
#pragma unroll
                for (int nt = 0; nt < 4; nt++)
                    mma_f16_16n8k16(acc[mt][nt], af[mt], bf[nt]);
        }
    }

#pragma unroll
    for (int mt = 0; mt < 4; mt++) {
#pragma unroll
        for (int nt = 0; nt < 4; nt++) {
            int row = m0 + wm * 64 + mt * 16 + gid;
            int col = n0 + wn * 32 + nt * 8 + 2 * tig;
            if (sizeof(OutT) == 4) {
                float* Cf = (float*)C;
                *(float2*)&Cf[(size_t)row * N + col] =
                    make_float2(acc[mt][nt][0] * scale, acc[mt][nt][1] * scale);
                *(float2*)&Cf[(size_t)(row + 8) * N + col] =
                    make_float2(acc[mt][nt][2] * scale, acc[mt][nt][3] * scale);
            } else {
                __half* Ch = (__half*)C;
                *(__half2*)&Ch[(size_t)row * N + col] =
                    __floats2half2_rn(acc[mt][nt][0] * scale, acc[mt][nt][1] * scale);
                *(__half2*)&Ch[(size_t)(row + 8) * N + col] =
                    __floats2half2_rn(acc[mt][nt][2] * scale, acc[mt][nt][3] * scale);
            }
        }
    }
}

// Fused QKV: grid (8, 64, 3)
__global__ __launch_bounds__(256)
void gemm_qkv_kernel(const __half* __restrict__ xh,
                     const __half* __restrict__ whBase,
                     __half* __restrict__ qh, __half* __restrict__ kh,
                     __half* __restrict__ vh) {
    extern __shared__ char smemc[];
    const int slot = blockIdx.z;
    const __half* Bw = whBase + (size_t)slot * DMODEL * DMODEL;
    __half* C = (slot == 0) ? qh : (slot == 1) ? kh : vh;
    const float scale = (slot == 0) ? 0.125f : 1.0f;
    gemm_body<__half>(xh, Bw, C, scale, smemc);
}

__global__ __launch_bounds__(256)
void gemm_out_kernel(const __half* __restrict__ A,
                     const __half* __restrict__ Bw,
                     float* __restrict__ C) {
    extern __shared__ char smemc[];
    gemm_body<float>(A, Bw, C, 1.0f, smemc);
}

// ===========================================================================
// Tensor-core flash attention (round-9 proven form, unchanged).
// grid (SEQ/128, NHEADS, BATCH), 128 threads = 4 warps; warp: 32 q-rows.
// ===========================================================================
#define FBKV 64
#define FSTR 72

__global__ __launch_bounds__(128)
void flash_tc_kernel(const __half* __restrict__ Qh,
                     const __half* __restrict__ Kh,
                     const __half* __restrict__ Vt,
                     const int*   __restrict__ am,
                     __half* __restrict__ O) {
    __shared__ __half Ks[2][FBKV * FSTR];
    __shared__ __half Vs[2][FBKV * FSTR];
    __shared__ float  Ms[2][FBKV];

    const int tid = threadIdx.x;
    const int wid = tid >> 5;
    const int lid = tid & 31;
    const int gid = lid >> 2;
    const int tig = lid & 3;
    const int q0  = blockIdx.x * 128;
    const int h   = blockIdx.y;
    const int b   = blockIdx.z;
    const int qw0 = q0 + wid * 32;

    const uint32_t ksa = smem_u32(Ks);
    const uint32_t vsa = smem_u32(Vs);
    const int b_row = (lid & 7) + ((lid >> 4) & 1) * 8;
    const int b_col = ((lid >> 3) & 1) * 8;

    uint32_t qf[2][4][4];
#pragma unroll
    for (int mt = 0; mt < 2; mt++)
#pragma unroll
        for (int kt = 0; kt < 4; kt++) {
            const __half* base = Qh + ((size_t)(b * SEQ) + qw0 + mt * 16 + gid) * DMODEL
                                    + h * 64 + kt * 16 + 2 * tig;
            qf[mt][kt][0] = *(const uint32_t*)base;
            qf[mt][kt][1] = *(const uint32_t*)(base + 8 * DMODEL);
            qf[mt][kt][2] = *(const uint32_t*)(base + 8);
            qf[mt][kt][3] = *(const uint32_t*)(base + 8 * DMODEL + 8);
        }

    float o[2][8][4];
#pragma unroll
    for (int mt = 0; mt < 2; mt++)
#pragma unroll
        for (int nt = 0; nt < 8; nt++)
#pragma unroll
            for (int r = 0; r < 4; r++) o[mt][nt][r] = 0.0f;
    float m_run[2][2] = { { -1e30f, -1e30f }, { -1e30f, -1e30f } };
    float lp[2][2]    = { { 0.0f, 0.0f }, { 0.0f, 0.0f } };

    const int nkb = (q0 + 128) / FBKV;

    auto issue = [&](int buf, int kb) {
        const int kv0 = kb * FBKV;
#pragma unroll
        for (int i = 0; i < 4; i++) {
            int idx = tid + i * 128;
            int row = idx >> 3;
            int c   = idx & 7;
            uint32_t so = (uint32_t)(buf * FBKV * FSTR + row * FSTR + c * 8) * 2;
            cp_async16(ksa + so,
                       Kh + ((size_t)(b * SEQ) + kv0 + row) * DMODEL + h * 64 + c * 8);
            cp_async16(vsa + so,
                       Vt + ((size_t)((b * 16 + h) * 64) + row) * SEQ + kv0 + c * 8);
        }
        CP_COMMIT();
        if (tid < FBKV)
            Ms[buf][tid] = am[b * SEQ + kv0 + tid] ? 0.0f : -1e30f;
    };

    issue(0, 0);

    for (int kb = 0; kb < nkb; kb++) {
        if (kb + 1 < nkb) { issue((kb + 1) & 1, kb + 1); CP_WAIT1(); }
        else              { CP_WAIT0(); }
        __syncthreads();

        const int buf = kb & 1;
        const int kv0 = kb * FBKV;
        const uint32_t kbase = ksa + (uint32_t)(buf * FBKV * FSTR) * 2;
        const uint32_t vbase = vsa + (uint32_t)(buf * FBKV * FSTR) * 2;

        if (kv0 <= qw0 + 31) {
            // ---- S = Q K^T ----
            float s[2][8][4];
#pragma unroll
            for (int mt = 0; mt < 2; mt++)
#pragma unroll
                for (int nt = 0; nt < 8; nt++)
#pragma unroll
                    for (int r = 0; r < 4; r++) s[mt][nt][r] = 0.0f;

#pragma unroll
            for (int kt = 0; kt < 4; kt++) {
                uint32_t bf[8][2];
#pragma unroll
                for (int p = 0; p < 4; p++) {
                    uint32_t ad = kbase + 2 * (uint32_t)((p * 16 + b_row) * FSTR
                                                         + kt * 16 + b_col);
                    ldsm_x4(bf[2 * p][0], bf[2 * p][1], bf[2 * p + 1][0],
                            bf[2 * p + 1][1], ad);
                }
#pragma unroll
                for (int mt = 0; mt < 2; mt++)
#pragma unroll
                    for (int nt = 0; nt < 8; nt++)
                        mma_f16_16n8k16(s[mt][nt], qf[mt][kt], bf[nt]);
            }

            // ---- mask + online softmax ----
#pragma unroll
            for (int mt = 0; mt < 2; mt++)
#pragma unroll
                for (int r = 0; r < 2; r++) {
                    const int row = qw0 + mt * 16 + gid + r * 8;
                    float mx = -1e30f;
#pragma unroll
                    for (int nt = 0; nt < 8; nt++)
#pragma unroll
                        for (int c = 0; c < 2; c++) {
                            const int jl = nt * 8 + 2 * tig + c;
                            float v = s[mt][nt][r * 2 + c] + Ms[buf][jl];
                            if (kv0 + jl > row) v = -1e30f;
                            s[mt][nt][r * 2 + c] = v;
                            mx = fmaxf(mx, v);
                        }
                    mx = fmaxf(mx, __shfl_xor_sync(0xffffffff, mx, 1));
                    mx = fmaxf(mx, __shfl_xor_sync(0xffffffff, mx, 2));
                    const float mnew = fmaxf(m_run[mt][r], mx);
                    const float corr = __expf(m_run[mt][r] - mnew);
                    m_run[mt][r] = mnew;
                    lp[mt][r] *= corr;
                    float ls = 0.0f;
#pragma unroll
                    for (int nt = 0; nt < 8; nt++) {
                        o[mt][nt][r * 2]     *= corr;
                        o[mt][nt][r * 2 + 1] *= corr;
                        float p0 = __expf(s[mt][nt][r * 2]     - mnew);
                        float p1 = __expf(s[mt][nt][r * 2 + 1] - mnew);
                        s[mt][nt][r * 2]     = p0;
                        s[mt][nt][r * 2 + 1] = p1;
                        ls += p0 + p1;
                    }
                    lp[mt][r] += ls;
                }

            // ---- O += P V ----
#pragma unroll
            for (int kt = 0; kt < 4; kt++) {
                uint32_t bfv[8][2];
#pragma unroll
                for (int p = 0; p < 4; p++) {
                    uint32_t ad = vbase + 2 * (uint32_t)((p * 16 + b_row) * FSTR
                                                         + kt * 16 + b_col);
                    ldsm_x4(bfv[2 * p][0], bfv[2 * p][1], bfv[2 * p + 1][0],
                            bfv[2 * p + 1][1], ad);
                }
#pragma unroll
                for (int mt = 0; mt < 2; mt++) {
                    uint32_t pa[4];
                    pa[0] = h2u(s[mt][2 * kt][0],     s[mt][2 * kt][1]);
                    pa[1] = h2u(s[mt][2 * kt][2],     s[mt][2 * kt][3]);
                    pa[2] = h2u(s[mt][2 * kt + 1][0], s[mt][2 * kt + 1][1]);
                    pa[3] = h2u(s[mt][2 * kt + 1][2], s[mt][2 * kt + 1][3]);
#pragma unroll
                    for (int nt = 0; nt < 8; nt++)
                        mma_f16_16n8k16(o[mt][nt], pa, bfv[nt]);
                }
            }
        }
        __syncthreads();
    }

    // ---- epilogue ----
#pragma unroll
    for (int mt = 0; mt < 2; mt++)
#pragma unroll
        for (int r = 0; r < 2; r++) {
            float l = lp[mt][r];
            l += __shfl_xor_sync(0xffffffff, l, 1);
            l += __shfl_xor_sync(0xffffffff, l, 2);
            const float inv = 1.0f / l;
            const int row = qw0 + mt * 16 + gid + r * 8;
            __half* orow = O + ((size_t)(b * SEQ) + row) * DMODEL + h * 64;
#pragma unroll
            for (int nt = 0; nt < 8; nt++)
                *(__half2*)&orow[nt * 8 + 2 * tig] =
                    __floats2half2_rn(o[mt][nt][r * 2] * inv,
                                      o[mt][nt][r * 2 + 1] * inv);
        }
}

// ---------------------------------------------------------------------------
extern "C" void kernel_launch(void* const* d_in, const int* in_sizes, int n_in,
                              void* d_out, int out_size) {
    const float* x  = (const float*)d_in[0];
    const int*   am = (const int*)  d_in[1];
    float* out = (float*)d_out;

    __half *xh, *qh, *kh, *vh, *vt, *oh, *wh;
    cudaGetSymbolAddress((void**)&xh, g_xh);
    cudaGetSymbolAddress((void**)&qh, g_qh);
    cudaGetSymbolAddress((void**)&kh, g_kh);
    cudaGetSymbolAddress((void**)&vh, g_vh);
    cudaGetSymbolAddress((void**)&vt, g_vt);
    cudaGetSymbolAddress((void**)&oh, g_oh);
    cudaGetSymbolAddress((void**)&wh, g_wh);

    cudaFuncSetAttribute(gemm_qkv_kernel,
                         cudaFuncAttributeMaxDynamicSharedMemorySize, SMEM_GEMM);
    cudaFuncSetAttribute(gemm_out_kernel,
                         cudaFuncAttributeMaxDynamicSharedMemorySize, SMEM_GEMM);

    {
        int n4 = XF4 + 4 * WF4;                  // 3145728 float4 total
        f2h_flat_kernel<<<(n4 + 255) / 256, 256>>>(
            x, (const float*)d_in[2], (const float*)d_in[3],
            (const float*)d_in[4], (const float*)d_in[5], xh, wh);
    }

    dim3 gq(DMODEL / GBN, MROWS / GBM, 3);    // (8, 64, 3)
    gemm_qkv_kernel<<<gq, 256, SMEM_GEMM>>>(xh, wh, qh, kh, vh);

    dim3 tg(SEQ / 64, NHEADS, BATCH);
    vtrans_kernel<<<tg, 256>>>(vh, vt);

    dim3 fg(SEQ / 128, NHEADS, BATCH);        // (16, 16, 4)
    flash_tc_kernel<<<fg, 128>>>(qh, kh, vt, am, oh);

    dim3 gg(DMODEL / GBN, MROWS / GBM);       // (8, 64)
    gemm_out_kernel<<<gg, 256, SMEM_GEMM>>>(
        oh, wh + 3 * (size_t)DMODEL * DMODEL, out);
}